// round 1
// baseline (speedup 1.0000x reference)
#include <cuda_runtime.h>
#include <math.h>

// ---------------- problem constants ----------------
#define BB   4
#define TT   4096
#define CC   1024
#define NH   16
#define DH   64
#define BT   (BB*TT)        // 16384
#define BTC  (BT*CC)        // 16777216
#define DMIX5 160
#define DDEC 64

// ---------------- scratch (static device memory; no allocs) ----------------
__device__ float g_dxprev[BTC];   // dxprev; reused as y after the scan
__device__ float g_xxx[BTC];      // xxx;    reused as y_ln after layernorm
__device__ float g_xr[BTC];
__device__ float g_xk[BTC];
__device__ float g_xv[BTC];
__device__ float g_xw[BTC];
__device__ float g_xv2[BTC];
__device__ float g_r[BTC];
__device__ float g_k[BTC];
__device__ float g_v[BTC];
__device__ float g_v2[BTC];
__device__ float g_w[BTC];        // w -> decay (in place)
__device__ float g_mixed[BT*DMIX5];
__device__ float g_aw[BT*DDEC];
__device__ float g_av2[BT*DDEC];

// ---------------- kernel 1: token shift prep ----------------
__global__ void __launch_bounds__(256) prep_kernel(
    const float* __restrict__ x, const float* __restrict__ shift,
    const float* __restrict__ maa_x)
{
    int idx = blockIdx.x * 256 + threadIdx.x;
    int c  = idx & (CC - 1);
    int bt = idx >> 10;
    int t  = bt & (TT - 1);
    int b  = bt >> 12;
    float xv    = x[idx];
    float xprev = (t == 0) ? shift[b * CC + c] : x[idx - CC];
    float dx = xprev - xv;
    g_dxprev[idx] = dx;
    g_xxx[idx]    = xv + dx * maa_x[c];
}

// ---------------- generic tiled SGEMM (row-major A[MxK] * B[KxN] = C[MxN]) ----------------
// EPI: 0 = none, 1 = tanh, 2 = C = extra[idx] + acc, 3 = C = extra[col] + acc (bias)
template<int EPI>
__global__ void __launch_bounds__(256) sgemm_kernel(
    const float* __restrict__ A, const float* __restrict__ Bm,
    float* __restrict__ Cm, const float* __restrict__ extra,
    int M, int N, int K)
{
    __shared__ float As[8][128];
    __shared__ float Bs[8][128];
    int bx = blockIdx.x, by = blockIdx.y;
    int tid = threadIdx.x;

    int aRow = tid >> 1, aCol = (tid & 1) << 2;
    int bRow = tid >> 5, bCol = (tid & 31) << 2;
    int ty = tid >> 4, tx = tid & 15;

    float acc[8][8];
#pragma unroll
    for (int m = 0; m < 8; m++)
#pragma unroll
        for (int n = 0; n < 8; n++) acc[m][n] = 0.f;

    const float* Ap = A + (size_t)(by * 128 + aRow) * K + aCol;
    int gcol = bx * 128 + bCol;
    const float* Bp = Bm + (size_t)bRow * N + gcol;
    bool bFull = (gcol + 3) < N;

    for (int k0 = 0; k0 < K; k0 += 8) {
        float4 a4 = *(const float4*)Ap;
        Ap += 8;
        As[aCol + 0][aRow] = a4.x;
        As[aCol + 1][aRow] = a4.y;
        As[aCol + 2][aRow] = a4.z;
        As[aCol + 3][aRow] = a4.w;

        float4 b4 = make_float4(0.f, 0.f, 0.f, 0.f);
        if (bFull) {
            b4 = *(const float4*)Bp;
        } else {
            if (gcol + 0 < N) b4.x = Bp[0];
            if (gcol + 1 < N) b4.y = Bp[1];
            if (gcol + 2 < N) b4.z = Bp[2];
            if (gcol + 3 < N) b4.w = Bp[3];
        }
        Bp += (size_t)8 * N;
        *(float4*)&Bs[bRow][bCol] = b4;

        __syncthreads();
#pragma unroll
        for (int kk = 0; kk < 8; kk++) {
            float ra[8], rb[8];
            *(float4*)&ra[0] = *(const float4*)&As[kk][ty * 8];
            *(float4*)&ra[4] = *(const float4*)&As[kk][ty * 8 + 4];
            *(float4*)&rb[0] = *(const float4*)&Bs[kk][tx * 8];
            *(float4*)&rb[4] = *(const float4*)&Bs[kk][tx * 8 + 4];
#pragma unroll
            for (int m = 0; m < 8; m++)
#pragma unroll
                for (int n = 0; n < 8; n++) acc[m][n] += ra[m] * rb[n];
        }
        __syncthreads();
    }

    int row0 = by * 128 + ty * 8;
    int col0 = bx * 128 + tx * 8;
#pragma unroll
    for (int m = 0; m < 8; m++) {
        int row = row0 + m;
        size_t base = (size_t)row * N;
#pragma unroll
        for (int n = 0; n < 8; n++) {
            int col = col0 + n;
            if (col < N) {
                float val = acc[m][n];
                if (EPI == 1) val = tanhf(val);
                if (EPI == 2) val += extra[base + col];
                if (EPI == 3) val += extra[col];
                Cm[base + col] = val;
            }
        }
    }
}

// ---------------- kernel 3: 5-way LoRA mix -> xr/xk/xv/xw/xv2 ----------------
__global__ void __launch_bounds__(256) mix_kernel(
    const float* __restrict__ x, const float* __restrict__ w2,
    const float* __restrict__ maa_r, const float* __restrict__ maa_k,
    const float* __restrict__ maa_v, const float* __restrict__ maa_w,
    const float* __restrict__ maa_v2)
{
    int f = blockIdx.y;
    int bt0 = blockIdx.x * 16;
    int tid = threadIdx.x;
    __shared__ float sm[16][32];
    for (int idx = tid; idx < 16 * 32; idx += 256) {
        int i = idx >> 5, d = idx & 31;
        sm[i][d] = g_mixed[(bt0 + i) * DMIX5 + f * 32 + d];
    }
    __syncthreads();

    const float* maa;
    float* outp;
    switch (f) {
        case 0: maa = maa_r;  outp = g_xr;  break;
        case 1: maa = maa_k;  outp = g_xk;  break;
        case 2: maa = maa_v;  outp = g_xv;  break;
        case 3: maa = maa_w;  outp = g_xw;  break;
        default: maa = maa_v2; outp = g_xv2; break;
    }

    for (int c0 = 0; c0 < CC; c0 += 256) {
        int c = c0 + tid;
        float w2col[32];
#pragma unroll
        for (int d = 0; d < 32; d++) w2col[d] = w2[(f * 32 + d) * CC + c];
        float maac = maa[c];
#pragma unroll 4
        for (int i = 0; i < 16; i++) {
            float m = 0.f;
#pragma unroll
            for (int d = 0; d < 32; d++) m += sm[i][d] * w2col[d];
            int gi = (bt0 + i) * CC + c;
            outp[gi] = x[gi] + g_dxprev[gi] * (maac + m);
        }
    }
}

// ---------------- kernel: decay epilogue ----------------
__global__ void __launch_bounds__(256) decay_kernel()
{
    int idx = blockIdx.x * 256 + threadIdx.x;
    float wv = g_w[idx];
    float dec = expf(-expf(wv));
    g_w[idx] = dec;
    g_k[idx] *= (1.0f - dec);
}

// ---------------- kernel: WKV scan ----------------
// grid: B*NH*4 = 256 blocks; block: 1024 threads.
// Block handles head (b,n) and a group of 16 value-columns (jg).
// Thread (jl,i) holds state[i][j], j = jg*16+jl.  Columns are independent.
__global__ void __launch_bounds__(1024, 1) scan_kernel(
    const float* __restrict__ state_in, float* __restrict__ state_out)
{
    int blk = blockIdx.x;
    int b  = blk >> 6;
    int n  = (blk >> 2) & 15;
    int jg = blk & 3;
    int tid = threadIdx.x;
    int jl = tid >> 6;
    int i  = tid & 63;
    int j  = jg * 16 + jl;

    float s = state_in[(((b * NH) + n) * 64 + i) * 64 + j];

    __shared__ float st[2][224];     // [0:64)=r [64:128)=k [128:192)=w [192:208)=v [208:224)=v2
    __shared__ float red[2][16][2];

    int headoff = b * TT * CC + n * 64;
    const float* src = nullptr;
    if      (tid < 64)  src = g_r  + headoff + tid;
    else if (tid < 128) src = g_k  + headoff + (tid - 64);
    else if (tid < 192) src = g_w  + headoff + (tid - 128);
    else if (tid < 208) src = g_v  + headoff + jg * 16 + (tid - 192);
    else if (tid < 224) src = g_v2 + headoff + jg * 16 + (tid - 208);

    float pre = (tid < 224) ? *src : 0.f;   // prefetch t = 0
    float* yout = g_dxprev + headoff + j;   // y scratch

    for (int t = 0; t < TT; ++t) {
        int p = t & 1;
        if (tid < 224) st[p][tid] = pre;
        __syncthreads();
        if (tid < 224 && t + 1 < TT) { src += CC; pre = *src; }  // prefetch t+1

        float rv  = st[p][i];
        float kv  = st[p][64 + i];
        float wv  = st[p][128 + i];
        float vv  = st[p][192 + jl];
        float v2v = st[p][208 + jl];

        float partial = rv * s;              // y uses state BEFORE update
        s = s * wv + kv * vv;                // state update

        partial += __shfl_down_sync(0xffffffffu, partial, 16);
        partial += __shfl_down_sync(0xffffffffu, partial, 8);
        partial += __shfl_down_sync(0xffffffffu, partial, 4);
        partial += __shfl_down_sync(0xffffffffu, partial, 2);
        partial += __shfl_down_sync(0xffffffffu, partial, 1);
        if ((i & 31) == 0) red[p][jl][i >> 5] = partial;
        __syncthreads();
        if (i == 0) yout[(size_t)t * CC] = red[p][jl][0] + red[p][jl][1] + v2v;
    }

    state_out[(((b * NH) + n) * 64 + i) * 64 + j] = s;
}

// ---------------- kernel: layernorm over C ----------------
__global__ void __launch_bounds__(128) ln_kernel(
    const float* __restrict__ g, const float* __restrict__ bvec)
{
    int row = blockIdx.x;
    int tid = threadIdx.x;
    const float* p = g_dxprev + (size_t)row * CC;   // y
    float v[8];
    float s = 0.f;
#pragma unroll
    for (int u = 0; u < 8; u++) { v[u] = p[tid + u * 128]; s += v[u]; }

    __shared__ float sb[4];
    for (int o = 16; o; o >>= 1) s += __shfl_xor_sync(0xffffffffu, s, o);
    if ((tid & 31) == 0) sb[tid >> 5] = s;
    __syncthreads();
    s = sb[0] + sb[1] + sb[2] + sb[3];
    float mu = s * (1.f / CC);

    float s2 = 0.f;
#pragma unroll
    for (int u = 0; u < 8; u++) { float d = v[u] - mu; s2 += d * d; }
    __shared__ float sb2[4];
    for (int o = 16; o; o >>= 1) s2 += __shfl_xor_sync(0xffffffffu, s2, o);
    if ((tid & 31) == 0) sb2[tid >> 5] = s2;
    __syncthreads();
    s2 = sb2[0] + sb2[1] + sb2[2] + sb2[3];
    float inv = rsqrtf(s2 * (1.f / CC) + 1e-5f);

#pragma unroll
    for (int u = 0; u < 8; u++) {
        int c = tid + u * 128;
        g_xxx[(size_t)row * CC + c] = (v[u] - mu) * inv * g[c] + bvec[c];  // y_ln scratch
    }
}

// ---------------- launch ----------------
extern "C" void kernel_launch(void* const* d_in, const int* in_sizes, int n_in,
                              void* d_out, int out_size)
{
    const float* x      = (const float*)d_in[0];
    const float* shift  = (const float*)d_in[1];
    const float* wkv0   = (const float*)d_in[2];
    const float* maa_x  = (const float*)d_in[3];
    const float* maa_r  = (const float*)d_in[4];
    const float* maa_k  = (const float*)d_in[5];
    const float* maa_v  = (const float*)d_in[6];
    const float* maa_w  = (const float*)d_in[7];
    const float* maa_v2 = (const float*)d_in[8];
    const float* w1     = (const float*)d_in[9];
    const float* w2     = (const float*)d_in[10];
    const float* tdec   = (const float*)d_in[11];
    const float* dw1    = (const float*)d_in[12];
    const float* dw2    = (const float*)d_in[13];
    const float* vw1    = (const float*)d_in[14];
    const float* vw2    = (const float*)d_in[15];
    const float* Wr     = (const float*)d_in[16];
    const float* Wk     = (const float*)d_in[17];
    const float* Wv     = (const float*)d_in[18];
    const float* Wo     = (const float*)d_in[19];
    const float* lng    = (const float*)d_in[20];
    const float* lnb    = (const float*)d_in[21];
    float* out = (float*)d_out;

    float *p_xxx, *p_xr, *p_xk, *p_xv, *p_xw, *p_xv2;
    float *p_r, *p_k, *p_v, *p_v2, *p_w, *p_mixed, *p_aw, *p_av2;
    cudaGetSymbolAddress((void**)&p_xxx,   g_xxx);
    cudaGetSymbolAddress((void**)&p_xr,    g_xr);
    cudaGetSymbolAddress((void**)&p_xk,    g_xk);
    cudaGetSymbolAddress((void**)&p_xv,    g_xv);
    cudaGetSymbolAddress((void**)&p_xw,    g_xw);
    cudaGetSymbolAddress((void**)&p_xv2,   g_xv2);
    cudaGetSymbolAddress((void**)&p_r,     g_r);
    cudaGetSymbolAddress((void**)&p_k,     g_k);
    cudaGetSymbolAddress((void**)&p_v,     g_v);
    cudaGetSymbolAddress((void**)&p_v2,    g_v2);
    cudaGetSymbolAddress((void**)&p_w,     g_w);
    cudaGetSymbolAddress((void**)&p_mixed, g_mixed);
    cudaGetSymbolAddress((void**)&p_aw,    g_aw);
    cudaGetSymbolAddress((void**)&p_av2,   g_av2);

    // 1. token shift + xxx
    prep_kernel<<<BTC / 256, 256>>>(x, shift, maa_x);
    // 2. mixed = tanh(xxx @ w1)   (16384 x 160 x 1024)
    sgemm_kernel<1><<<dim3(2, 128), 256>>>(p_xxx, w1, p_mixed, nullptr, BT, DMIX5, CC);
    // 3. xr/xk/xv/xw/xv2
    mix_kernel<<<dim3(BT / 16, 5), 256>>>(x, w2, maa_r, maa_k, maa_v, maa_w, maa_v2);
    // 4. big projections (16384 x 1024 x 1024)
    sgemm_kernel<0><<<dim3(8, 128), 256>>>(p_xr,  Wr, p_r,  nullptr, BT, CC, CC);
    sgemm_kernel<0><<<dim3(8, 128), 256>>>(p_xk,  Wk, p_k,  nullptr, BT, CC, CC);
    sgemm_kernel<0><<<dim3(8, 128), 256>>>(p_xv,  Wv, p_v,  nullptr, BT, CC, CC);
    sgemm_kernel<0><<<dim3(8, 128), 256>>>(p_xv2, Wv, p_v2, nullptr, BT, CC, CC);
    // 5. decay LoRA: aw = tanh(xw @ dw1); w = tdec + aw @ dw2
    sgemm_kernel<1><<<dim3(1, 128), 256>>>(p_xw, dw1, p_aw, nullptr, BT, DDEC, CC);
    sgemm_kernel<3><<<dim3(8, 128), 256>>>(p_aw, dw2, p_w, tdec, BT, CC, DDEC);
    // 6. v2 LoRA: av2 = tanh(xv2 @ vw1); v2 += av2 @ vw2
    sgemm_kernel<1><<<dim3(1, 128), 256>>>(p_xv2, vw1, p_av2, nullptr, BT, DDEC, CC);
    sgemm_kernel<2><<<dim3(8, 128), 256>>>(p_av2, vw2, p_v2, p_v2, BT, CC, DDEC);
    // 7. decay = exp(-exp(w)); k *= (1-decay)
    decay_kernel<<<BTC / 256, 256>>>();
    // 8. WKV scan -> y (g_dxprev), final state -> out[BTC:]
    scan_kernel<<<256, 1024>>>(wkv0, out + BTC);
    // 9. layernorm -> y_ln (g_xxx)
    ln_kernel<<<BT, 128>>>(lng, lnb);
    // 10. y_ln @ W_o -> out
    sgemm_kernel<0><<<dim3(8, 128), 256>>>(p_xxx, Wo, out, nullptr, BT, CC, CC);
}

// round 3
// speedup vs baseline: 1.6016x; 1.6016x over previous
#include <cuda_runtime.h>
#include <math.h>
#include <stdint.h>

// ---------------- problem constants ----------------
#define BB   4
#define TT   4096
#define CC   1024
#define NH   16
#define DH   64
#define BT   (BB*TT)        // 16384
#define BTC  (BT*CC)        // 16777216
#define DMIX5 160
#define DDEC 64

// ---------------- scratch (static device memory; no allocs) ----------------
__device__ float g_dxprev[BTC];   // dxprev; reused as y after the scan
__device__ float g_xxx[BTC];      // xxx;    reused as y_ln after layernorm
__device__ float g_xr[BTC];
__device__ float g_xk[BTC];
__device__ float g_xv[BTC];
__device__ float g_xw[BTC];
__device__ float g_xv2[BTC];
__device__ float g_r[BTC];
__device__ float g_k[BTC];
__device__ float g_v[BTC];
__device__ float g_v2[BTC];
__device__ float g_w[BTC];        // w -> decay (in place)
__device__ float g_mixed[BT*DMIX5];
__device__ float g_aw[BT*DDEC];
__device__ float g_av2[BT*DDEC];
__device__ float g_WtR[CC*CC];    // transposed weights (K-major B operands)
__device__ float g_WtK[CC*CC];
__device__ float g_WtV[CC*CC];
__device__ float g_WtO[CC*CC];
__device__ float g_dw2t[CC*DDEC];
__device__ float g_vw2t[CC*DDEC];

// ================= PTX helpers (cp.async + mma.sync, sm_100 base target) =================
__device__ __forceinline__ uint32_t smem_u32(const void* p) {
    uint32_t a;
    asm("{ .reg .u64 t; cvta.to.shared.u64 t, %1; cvt.u32.u64 %0, t; }" : "=r"(a) : "l"(p));
    return a;
}
__device__ __forceinline__ void cp_async16(uint32_t dst, const void* src) {
    asm volatile("cp.async.cg.shared.global [%0], [%1], 16;" :: "r"(dst), "l"(src) : "memory");
}
#define CP_COMMIT() asm volatile("cp.async.commit_group;" ::: "memory")
template<int N> __device__ __forceinline__ void cp_wait() {
    asm volatile("cp.async.wait_group %0;" :: "n"(N) : "memory");
}
__device__ __forceinline__ uint32_t f2tf(float f) {
    uint32_t r;
    asm("cvt.rna.tf32.f32 %0, %1;" : "=r"(r) : "f"(f));
    return r;
}
__device__ __forceinline__ void mma_tf32(float* c, const uint32_t* a, const uint32_t* b) {
    asm volatile(
        "mma.sync.aligned.m16n8k8.row.col.f32.tf32.tf32.f32 "
        "{%0,%1,%2,%3}, {%4,%5,%6,%7}, {%8,%9}, {%0,%1,%2,%3};"
        : "+f"(c[0]), "+f"(c[1]), "+f"(c[2]), "+f"(c[3])
        : "r"(a[0]), "r"(a[1]), "r"(a[2]), "r"(a[3]), "r"(b[0]), "r"(b[1]));
}

// ================= tf32 mma.sync GEMM =================
// C[M,N] = A[M,K] * Bt[N,K]^T ; tiles: BM=128, BN=128, BK=32; 256 threads (8 warps 2x4).
// smem stage: A 128x36f + B 128x36f (stride 36 -> conflict-free, 16B-aligned rows).
// EPI: 0 none, 2 C = extra[idx] + acc, 3 C = extra[col] + acc
#define MSTAGE_F (2*128*36)          // floats per stage
#define MSMEM_BYTES (3*MSTAGE_F*4)   // 110592 B

template<int EPI>
__global__ void __launch_bounds__(256, 1) mma_gemm_kernel(
    const float* __restrict__ A, const float* __restrict__ Bt,
    float* __restrict__ Cm, const float* __restrict__ extra,
    int K, int N)
{
    extern __shared__ float sm[];
    const int tid = threadIdx.x;
    const int wid = tid >> 5;
    const int lane = tid & 31;
    const int wm = wid & 1;          // warp row (2)
    const int wn = wid >> 1;         // warp col (4)
    const int g = lane >> 2;
    const int t = lane & 3;
    const int m0 = blockIdx.y * 128;
    const int n0 = blockIdx.x * 128;

    const float* gA = A + (size_t)m0 * K;
    const float* gB = Bt + (size_t)n0 * K;
    const int NC = K / 32;
    const uint32_t smb = smem_u32(sm);

    float cf[4][4][4];
#pragma unroll
    for (int am = 0; am < 4; am++)
#pragma unroll
        for (int an = 0; an < 4; an++)
#pragma unroll
            for (int q = 0; q < 4; q++) cf[am][an][q] = 0.f;

    auto stage = [&](int s, int c) {
        uint32_t sa = smb + (uint32_t)(s * MSTAGE_F * 4);
        uint32_t sbB = sa + 128 * 36 * 4;
        const float* srcA = gA + c * 32;
        const float* srcB = gB + c * 32;
#pragma unroll
        for (int i = 0; i < 4; i++) {
            int q = i * 256 + tid;
            int m = q >> 3, seg = q & 7;
            cp_async16(sa + (uint32_t)(m * 144 + seg * 16), srcA + (size_t)m * K + seg * 4);
        }
#pragma unroll
        for (int i = 0; i < 4; i++) {
            int q = i * 256 + tid;
            int m = q >> 3, seg = q & 7;
            cp_async16(sbB + (uint32_t)(m * 144 + seg * 16), srcB + (size_t)m * K + seg * 4);
        }
        CP_COMMIT();
    };

    stage(0, 0);
    if (NC > 1) stage(1, 1); else CP_COMMIT();

    for (int c = 0; c < NC; c++) {
        if (c + 1 < NC) cp_wait<1>(); else cp_wait<0>();
        __syncthreads();
        if (c + 2 < NC) stage((c + 2) % 3, c + 2);

        const float* As = sm + (c % 3) * MSTAGE_F;
        const float* Bs = As + 128 * 36;
#pragma unroll
        for (int kk = 0; kk < 32; kk += 8) {
            uint32_t a[4][4], b[4][2];
#pragma unroll
            for (int am = 0; am < 4; am++) {
                const float* p = As + (wm * 64 + am * 16 + g) * 36 + kk + t;
                a[am][0] = f2tf(p[0]);
                a[am][1] = f2tf(p[8 * 36]);
                a[am][2] = f2tf(p[4]);
                a[am][3] = f2tf(p[8 * 36 + 4]);
            }
#pragma unroll
            for (int an = 0; an < 4; an++) {
                const float* p = Bs + (wn * 32 + an * 8 + g) * 36 + kk + t;
                b[an][0] = f2tf(p[0]);
                b[an][1] = f2tf(p[4]);
            }
#pragma unroll
            for (int am = 0; am < 4; am++)
#pragma unroll
                for (int an = 0; an < 4; an++)
                    mma_tf32(cf[am][an], a[am], b[an]);
        }
        __syncthreads();
    }

    // epilogue: direct register -> gmem float2 stores
#pragma unroll
    for (int am = 0; am < 4; am++) {
        int row = m0 + wm * 64 + am * 16 + g;
#pragma unroll
        for (int an = 0; an < 4; an++) {
            int col = n0 + wn * 32 + an * 8 + 2 * t;
            float2 v0 = make_float2(cf[am][an][0], cf[am][an][1]);
            float2 v1 = make_float2(cf[am][an][2], cf[am][an][3]);
            if (EPI == 2) {
                float2 e0 = *(const float2*)(extra + (size_t)row * N + col);
                float2 e1 = *(const float2*)(extra + (size_t)(row + 8) * N + col);
                v0.x += e0.x; v0.y += e0.y;
                v1.x += e1.x; v1.y += e1.y;
            }
            if (EPI == 3) {
                v0.x += extra[col];     v0.y += extra[col + 1];
                v1.x += extra[col];     v1.y += extra[col + 1];
            }
            *(float2*)(Cm + (size_t)row * N + col) = v0;
            *(float2*)(Cm + (size_t)(row + 8) * N + col) = v1;
        }
    }
}

// ---------------- generic transpose: dst[c][r] = src[r][c], dims multiples of 32 --------
__global__ void __launch_bounds__(256) transpose_kernel(
    const float* __restrict__ src, float* __restrict__ dst, int R, int C)
{
    __shared__ float tbuf[32][33];
    int bx = blockIdx.x * 32, by = blockIdx.y * 32;
    int txx = threadIdx.x, tyy = threadIdx.y;
#pragma unroll
    for (int i = 0; i < 32; i += 8)
        tbuf[tyy + i][txx] = src[(size_t)(by + tyy + i) * C + bx + txx];
    __syncthreads();
#pragma unroll
    for (int i = 0; i < 32; i += 8)
        dst[(size_t)(bx + tyy + i) * R + by + txx] = tbuf[txx][tyy + i];
}

// ---------------- kernel 1: token shift prep ----------------
__global__ void __launch_bounds__(256) prep_kernel(
    const float* __restrict__ x, const float* __restrict__ shift,
    const float* __restrict__ maa_x)
{
    int idx = blockIdx.x * 256 + threadIdx.x;
    int c  = idx & (CC - 1);
    int bt = idx >> 10;
    int t  = bt & (TT - 1);
    int b  = bt >> 12;
    float xv    = x[idx];
    float xprev = (t == 0) ? shift[b * CC + c] : x[idx - CC];
    float dx = xprev - xv;
    g_dxprev[idx] = dx;
    g_xxx[idx]    = xv + dx * maa_x[c];
}

// ---------------- fp32 tiled SGEMM (tanh LoRA GEMMs only) ----------------
// EPI: 1 = tanh
template<int EPI>
__global__ void __launch_bounds__(256) sgemm_kernel(
    const float* __restrict__ A, const float* __restrict__ Bm,
    float* __restrict__ Cm, const float* __restrict__ extra,
    int M, int N, int K)
{
    __shared__ float As[8][128];
    __shared__ float Bs[8][128];
    int bx = blockIdx.x, by = blockIdx.y;
    int tid = threadIdx.x;

    int aRow = tid >> 1, aCol = (tid & 1) << 2;
    int bRow = tid >> 5, bCol = (tid & 31) << 2;
    int ty = tid >> 4, tx = tid & 15;

    float acc[8][8];
#pragma unroll
    for (int m = 0; m < 8; m++)
#pragma unroll
        for (int n = 0; n < 8; n++) acc[m][n] = 0.f;

    const float* Ap = A + (size_t)(by * 128 + aRow) * K + aCol;
    int gcol = bx * 128 + bCol;
    const float* Bp = Bm + (size_t)bRow * N + gcol;
    bool bFull = (gcol + 3) < N;

    for (int k0 = 0; k0 < K; k0 += 8) {
        float4 a4 = *(const float4*)Ap;
        Ap += 8;
        As[aCol + 0][aRow] = a4.x;
        As[aCol + 1][aRow] = a4.y;
        As[aCol + 2][aRow] = a4.z;
        As[aCol + 3][aRow] = a4.w;

        float4 b4 = make_float4(0.f, 0.f, 0.f, 0.f);
        if (bFull) {
            b4 = *(const float4*)Bp;
        } else {
            if (gcol + 0 < N) b4.x = Bp[0];
            if (gcol + 1 < N) b4.y = Bp[1];
            if (gcol + 2 < N) b4.z = Bp[2];
            if (gcol + 3 < N) b4.w = Bp[3];
        }
        Bp += (size_t)8 * N;
        *(float4*)&Bs[bRow][bCol] = b4;

        __syncthreads();
#pragma unroll
        for (int kk = 0; kk < 8; kk++) {
            float ra[8], rb[8];
            *(float4*)&ra[0] = *(const float4*)&As[kk][ty * 8];
            *(float4*)&ra[4] = *(const float4*)&As[kk][ty * 8 + 4];
            *(float4*)&rb[0] = *(const float4*)&Bs[kk][tx * 8];
            *(float4*)&rb[4] = *(const float4*)&Bs[kk][tx * 8 + 4];
#pragma unroll
            for (int m = 0; m < 8; m++)
#pragma unroll
                for (int n = 0; n < 8; n++) acc[m][n] += ra[m] * rb[n];
        }
        __syncthreads();
    }

    int row0 = by * 128 + ty * 8;
    int col0 = bx * 128 + tx * 8;
#pragma unroll
    for (int m = 0; m < 8; m++) {
        int row = row0 + m;
        size_t base = (size_t)row * N;
#pragma unroll
        for (int n = 0; n < 8; n++) {
            int col = col0 + n;
            if (col < N) {
                float val = acc[m][n];
                if (EPI == 1) val = tanhf(val);
                Cm[base + col] = val;
            }
        }
    }
}

// ---------------- kernel 3: 5-way LoRA mix -> xr/xk/xv/xw/xv2 ----------------
__global__ void __launch_bounds__(256) mix_kernel(
    const float* __restrict__ x, const float* __restrict__ w2,
    const float* __restrict__ maa_r, const float* __restrict__ maa_k,
    const float* __restrict__ maa_v, const float* __restrict__ maa_w,
    const float* __restrict__ maa_v2)
{
    int f = blockIdx.y;
    int bt0 = blockIdx.x * 16;
    int tid = threadIdx.x;
    __shared__ float sm[16][32];
    for (int idx = tid; idx < 16 * 32; idx += 256) {
        int i = idx >> 5, d = idx & 31;
        sm[i][d] = g_mixed[(bt0 + i) * DMIX5 + f * 32 + d];
    }
    __syncthreads();

    const float* maa;
    float* outp;
    switch (f) {
        case 0: maa = maa_r;  outp = g_xr;  break;
        case 1: maa = maa_k;  outp = g_xk;  break;
        case 2: maa = maa_v;  outp = g_xv;  break;
        case 3: maa = maa_w;  outp = g_xw;  break;
        default: maa = maa_v2; outp = g_xv2; break;
    }

    for (int c0 = 0; c0 < CC; c0 += 256) {
        int c = c0 + tid;
        float w2col[32];
#pragma unroll
        for (int d = 0; d < 32; d++) w2col[d] = w2[(f * 32 + d) * CC + c];
        float maac = maa[c];
#pragma unroll 4
        for (int i = 0; i < 16; i++) {
            float m = 0.f;
#pragma unroll
            for (int d = 0; d < 32; d++) m += sm[i][d] * w2col[d];
            int gi = (bt0 + i) * CC + c;
            outp[gi] = x[gi] + g_dxprev[gi] * (maac + m);
        }
    }
}

// ---------------- kernel: decay epilogue ----------------
__global__ void __launch_bounds__(256) decay_kernel()
{
    int idx = blockIdx.x * 256 + threadIdx.x;
    float wv = g_w[idx];
    float dec = expf(-expf(wv));
    g_w[idx] = dec;
    g_k[idx] *= (1.0f - dec);
}

// ---------------- kernel: WKV scan ----------------
__global__ void __launch_bounds__(1024, 1) scan_kernel(
    const float* __restrict__ state_in, float* __restrict__ state_out)
{
    int blk = blockIdx.x;
    int b  = blk >> 6;
    int n  = (blk >> 2) & 15;
    int jg = blk & 3;
    int tid = threadIdx.x;
    int jl = tid >> 6;
    int i  = tid & 63;
    int j  = jg * 16 + jl;

    float s = state_in[(((b * NH) + n) * 64 + i) * 64 + j];

    __shared__ float st[2][224];
    __shared__ float red[2][16][2];

    int headoff = b * TT * CC + n * 64;
    const float* src = nullptr;
    if      (tid < 64)  src = g_r  + headoff + tid;
    else if (tid < 128) src = g_k  + headoff + (tid - 64);
    else if (tid < 192) src = g_w  + headoff + (tid - 128);
    else if (tid < 208) src = g_v  + headoff + jg * 16 + (tid - 192);
    else if (tid < 224) src = g_v2 + headoff + jg * 16 + (tid - 208);

    float pre = (tid < 224) ? *src : 0.f;
    float* yout = g_dxprev + headoff + j;

    for (int t = 0; t < TT; ++t) {
        int p = t & 1;
        if (tid < 224) st[p][tid] = pre;
        __syncthreads();
        if (tid < 224 && t + 1 < TT) { src += CC; pre = *src; }

        float rv  = st[p][i];
        float kv  = st[p][64 + i];
        float wv  = st[p][128 + i];
        float vv  = st[p][192 + jl];
        float v2v = st[p][208 + jl];

        float partial = rv * s;
        s = s * wv + kv * vv;

        partial += __shfl_down_sync(0xffffffffu, partial, 16);
        partial += __shfl_down_sync(0xffffffffu, partial, 8);
        partial += __shfl_down_sync(0xffffffffu, partial, 4);
        partial += __shfl_down_sync(0xffffffffu, partial, 2);
        partial += __shfl_down_sync(0xffffffffu, partial, 1);
        if ((i & 31) == 0) red[p][jl][i >> 5] = partial;
        __syncthreads();
        if (i == 0) yout[(size_t)t * CC] = red[p][jl][0] + red[p][jl][1] + v2v;
    }

    state_out[(((b * NH) + n) * 64 + i) * 64 + j] = s;
}

// ---------------- kernel: layernorm over C ----------------
__global__ void __launch_bounds__(128) ln_kernel(
    const float* __restrict__ g, const float* __restrict__ bvec)
{
    int row = blockIdx.x;
    int tid = threadIdx.x;
    const float* p = g_dxprev + (size_t)row * CC;
    float v[8];
    float s = 0.f;
#pragma unroll
    for (int u = 0; u < 8; u++) { v[u] = p[tid + u * 128]; s += v[u]; }

    __shared__ float sb[4];
    for (int o = 16; o; o >>= 1) s += __shfl_xor_sync(0xffffffffu, s, o);
    if ((tid & 31) == 0) sb[tid >> 5] = s;
    __syncthreads();
    s = sb[0] + sb[1] + sb[2] + sb[3];
    float mu = s * (1.f / CC);

    float s2 = 0.f;
#pragma unroll
    for (int u = 0; u < 8; u++) { float d = v[u] - mu; s2 += d * d; }
    __shared__ float sb2[4];
    for (int o = 16; o; o >>= 1) s2 += __shfl_xor_sync(0xffffffffu, s2, o);
    if ((tid & 31) == 0) sb2[tid >> 5] = s2;
    __syncthreads();
    s2 = sb2[0] + sb2[1] + sb2[2] + sb2[3];
    float inv = rsqrtf(s2 * (1.f / CC) + 1e-5f);

#pragma unroll
    for (int u = 0; u < 8; u++) {
        int c = tid + u * 128;
        g_xxx[(size_t)row * CC + c] = (v[u] - mu) * inv * g[c] + bvec[c];
    }
}

// ---------------- launch ----------------
extern "C" void kernel_launch(void* const* d_in, const int* in_sizes, int n_in,
                              void* d_out, int out_size)
{
    const float* x      = (const float*)d_in[0];
    const float* shift  = (const float*)d_in[1];
    const float* wkv0   = (const float*)d_in[2];
    const float* maa_x  = (const float*)d_in[3];
    const float* maa_r  = (const float*)d_in[4];
    const float* maa_k  = (const float*)d_in[5];
    const float* maa_v  = (const float*)d_in[6];
    const float* maa_w  = (const float*)d_in[7];
    const float* maa_v2 = (const float*)d_in[8];
    const float* w1     = (const float*)d_in[9];
    const float* w2     = (const float*)d_in[10];
    const float* tdec   = (const float*)d_in[11];
    const float* dw1    = (const float*)d_in[12];
    const float* dw2    = (const float*)d_in[13];
    const float* vw1    = (const float*)d_in[14];
    const float* vw2    = (const float*)d_in[15];
    const float* Wr     = (const float*)d_in[16];
    const float* Wk     = (const float*)d_in[17];
    const float* Wv     = (const float*)d_in[18];
    const float* Wo     = (const float*)d_in[19];
    const float* lng    = (const float*)d_in[20];
    const float* lnb    = (const float*)d_in[21];
    float* out = (float*)d_out;

    float *p_xxx, *p_xr, *p_xk, *p_xv, *p_xw, *p_xv2;
    float *p_r, *p_k, *p_v, *p_v2, *p_w, *p_mixed, *p_aw, *p_av2;
    float *p_WtR, *p_WtK, *p_WtV, *p_WtO, *p_dw2t, *p_vw2t;
    cudaGetSymbolAddress((void**)&p_xxx,   g_xxx);
    cudaGetSymbolAddress((void**)&p_xr,    g_xr);
    cudaGetSymbolAddress((void**)&p_xk,    g_xk);
    cudaGetSymbolAddress((void**)&p_xv,    g_xv);
    cudaGetSymbolAddress((void**)&p_xw,    g_xw);
    cudaGetSymbolAddress((void**)&p_xv2,   g_xv2);
    cudaGetSymbolAddress((void**)&p_r,     g_r);
    cudaGetSymbolAddress((void**)&p_k,     g_k);
    cudaGetSymbolAddress((void**)&p_v,     g_v);
    cudaGetSymbolAddress((void**)&p_v2,    g_v2);
    cudaGetSymbolAddress((void**)&p_w,     g_w);
    cudaGetSymbolAddress((void**)&p_mixed, g_mixed);
    cudaGetSymbolAddress((void**)&p_aw,    g_aw);
    cudaGetSymbolAddress((void**)&p_av2,   g_av2);
    cudaGetSymbolAddress((void**)&p_WtR,   g_WtR);
    cudaGetSymbolAddress((void**)&p_WtK,   g_WtK);
    cudaGetSymbolAddress((void**)&p_WtV,   g_WtV);
    cudaGetSymbolAddress((void**)&p_WtO,   g_WtO);
    cudaGetSymbolAddress((void**)&p_dw2t,  g_dw2t);
    cudaGetSymbolAddress((void**)&p_vw2t,  g_vw2t);

    cudaFuncSetAttribute(mma_gemm_kernel<0>,
                         cudaFuncAttributeMaxDynamicSharedMemorySize, MSMEM_BYTES);
    cudaFuncSetAttribute(mma_gemm_kernel<2>,
                         cudaFuncAttributeMaxDynamicSharedMemorySize, MSMEM_BYTES);
    cudaFuncSetAttribute(mma_gemm_kernel<3>,
                         cudaFuncAttributeMaxDynamicSharedMemorySize, MSMEM_BYTES);

    dim3 tblk(32, 8);
    transpose_kernel<<<dim3(32, 32), tblk>>>(Wr, p_WtR, CC, CC);
    transpose_kernel<<<dim3(32, 32), tblk>>>(Wk, p_WtK, CC, CC);
    transpose_kernel<<<dim3(32, 32), tblk>>>(Wv, p_WtV, CC, CC);
    transpose_kernel<<<dim3(32, 32), tblk>>>(Wo, p_WtO, CC, CC);
    transpose_kernel<<<dim3(32, 2),  tblk>>>(dw2, p_dw2t, DDEC, CC);
    transpose_kernel<<<dim3(32, 2),  tblk>>>(vw2, p_vw2t, DDEC, CC);

    // 1. token shift + xxx
    prep_kernel<<<BTC / 256, 256>>>(x, shift, maa_x);
    // 2. mixed = tanh(xxx @ w1)   (16384 x 160 x 1024)
    sgemm_kernel<1><<<dim3(2, 128), 256>>>(p_xxx, w1, p_mixed, nullptr, BT, DMIX5, CC);
    // 3. xr/xk/xv/xw/xv2
    mix_kernel<<<dim3(BT / 16, 5), 256>>>(x, w2, maa_r, maa_k, maa_v, maa_w, maa_v2);
    // 4. big projections via tf32 mma.sync (16384 x 1024 x 1024)
    dim3 ggrid(CC / 128, BT / 128);   // (8, 128)
    mma_gemm_kernel<0><<<ggrid, 256, MSMEM_BYTES>>>(p_xr,  p_WtR, p_r,  nullptr, CC, CC);
    mma_gemm_kernel<0><<<ggrid, 256, MSMEM_BYTES>>>(p_xk,  p_WtK, p_k,  nullptr, CC, CC);
    mma_gemm_kernel<0><<<ggrid, 256, MSMEM_BYTES>>>(p_xv,  p_WtV, p_v,  nullptr, CC, CC);
    mma_gemm_kernel<0><<<ggrid, 256, MSMEM_BYTES>>>(p_xv2, p_WtV, p_v2, nullptr, CC, CC);
    // 5. decay LoRA: aw = tanh(xw @ dw1); w = tdec + aw @ dw2
    sgemm_kernel<1><<<dim3(1, 128), 256>>>(p_xw, dw1, p_aw, nullptr, BT, DDEC, CC);
    mma_gemm_kernel<3><<<ggrid, 256, MSMEM_BYTES>>>(p_aw, p_dw2t, p_w, tdec, DDEC, CC);
    // 6. v2 LoRA: av2 = tanh(xv2 @ vw1); v2 += av2 @ vw2
    sgemm_kernel<1><<<dim3(1, 128), 256>>>(p_xv2, vw1, p_av2, nullptr, BT, DDEC, CC);
    mma_gemm_kernel<2><<<ggrid, 256, MSMEM_BYTES>>>(p_av2, p_vw2t, p_v2, p_v2, DDEC, CC);
    // 7. decay = exp(-exp(w)); k *= (1-decay)
    decay_kernel<<<BTC / 256, 256>>>();
    // 8. WKV scan -> y (g_dxprev), final state -> out[BTC:]
    scan_kernel<<<256, 1024>>>(wkv0, out + BTC);
    // 9. layernorm -> y_ln (g_xxx)
    ln_kernel<<<BT, 128>>>(lng, lnb);
    // 10. y_ln @ W_o -> out
    mma_gemm_kernel<0><<<ggrid, 256, MSMEM_BYTES>>>(p_xxx, p_WtO, out, nullptr, CC, CC);
}